// round 9
// baseline (speedup 1.0000x reference)
#include <cuda_runtime.h>
#include <cuda_bf16.h>
#include <cstdint>

#define NNODES 25000
#define NEDGES 400000
#define DIM    1024
#define MPAD   25088          // 98 * 256
#define KDUAL  2048
#define BK     64
#define NSTAGE (KDUAL / BK)   // 32
#define STAGE_BYTES 98304     // Ahi 32K + Alo 32K + Bhi 16K + Blo 16K
#define SMEMSZ (2 * STAGE_BYTES + 1024)

// ---------------- device scratch ---------------------------------------------
__device__ int   g_deg[NNODES];
__device__ float g_deginv[NNODES];
__device__ int   g_rowptr[NNODES + 1];
__device__ int   g_fill[NNODES];
__device__ int   g_col[NEDGES];
__device__ __align__(256) __nv_bfloat16 g_A0hi[(size_t)MPAD * KDUAL];
__device__ __align__(256) __nv_bfloat16 g_A0lo[(size_t)MPAD * KDUAL];
__device__ __align__(256) __nv_bfloat16 g_A1hi[(size_t)MPAD * KDUAL];
__device__ __align__(256) __nv_bfloat16 g_A1lo[(size_t)MPAD * KDUAL];
__device__ __align__(256) __nv_bfloat16 g_Bhi[(size_t)DIM * KDUAL];   // [N][K] = W^T
__device__ __align__(256) __nv_bfloat16 g_Blo[(size_t)DIM * KDUAL];

// ---------------- helpers ------------------------------------------------------
__device__ __forceinline__ uint32_t smem_u32_of(const void* p) {
    uint32_t a;
    asm("{ .reg .u64 t; cvta.to.shared.u64 t, %1; cvt.u32.u64 %0, t; }" : "=r"(a) : "l"(p));
    return a;
}

__device__ __forceinline__ uint32_t sw128(uint32_t off) {
    return off ^ ((off >> 3) & 0x70);
}

__device__ __forceinline__ void cp_async16(uint32_t saddr, const void* g) {
    asm volatile("cp.async.cg.shared.global [%0], [%1], 16;" :: "r"(saddr), "l"(g));
}

__device__ __forceinline__ void ldsm_x4(uint32_t* r, uint32_t addr) {
    asm volatile("ldmatrix.sync.aligned.m8n8.x4.shared.b16 {%0,%1,%2,%3}, [%4];"
                 : "=r"(r[0]), "=r"(r[1]), "=r"(r[2]), "=r"(r[3]) : "r"(addr));
}

__device__ __forceinline__ void mma_bf16(float* d, const uint32_t* a, const uint32_t* b) {
    asm volatile(
        "mma.sync.aligned.m16n8k16.row.col.f32.bf16.bf16.f32 "
        "{%0,%1,%2,%3}, {%4,%5,%6,%7}, {%8,%9}, {%0,%1,%2,%3};"
        : "+f"(d[0]), "+f"(d[1]), "+f"(d[2]), "+f"(d[3])
        : "r"(a[0]), "r"(a[1]), "r"(a[2]), "r"(a[3]), "r"(b[0]), "r"(b[1]));
}

// ---------------- CSR build ---------------------------------------------------
__global__ void zero_deg_kernel() {
    int i = blockIdx.x * blockDim.x + threadIdx.x;
    if (i < NNODES) g_deg[i] = 0;
}

__global__ void count_deg_kernel(const int* __restrict__ edge_dst) {
    int e = blockIdx.x * blockDim.x + threadIdx.x;
    if (e < NEDGES) atomicAdd(&g_deg[edge_dst[e]], 1);
}

__global__ void build_rowptr_kernel() {
    __shared__ int sums[1024];
    const int tid = threadIdx.x;
    const int CHUNK = 25;
    const int start = tid * CHUNK;
    int s = 0;
    for (int i = 0; i < CHUNK; ++i) {
        int idx = start + i;
        if (idx < NNODES) s += g_deg[idx];
    }
    sums[tid] = s;
    __syncthreads();
    for (int off = 1; off < 1024; off <<= 1) {
        int add = 0;
        if (tid >= off) add = sums[tid - off];
        __syncthreads();
        sums[tid] += add;
        __syncthreads();
    }
    int prefix = (tid > 0) ? sums[tid - 1] : 0;
    for (int i = 0; i < CHUNK; ++i) {
        int idx = start + i;
        if (idx < NNODES) {
            g_rowptr[idx] = prefix;
            int d = g_deg[idx];
            prefix += d;
            g_deginv[idx] = 1.0f / fmaxf((float)d, 1.0f);
            g_fill[idx] = 0;
        }
    }
    if (tid == 1023) g_rowptr[NNODES] = sums[1023];
}

__global__ void fill_csr_kernel(const int* __restrict__ edge_src,
                                const int* __restrict__ edge_dst) {
    int e = blockIdx.x * blockDim.x + threadIdx.x;
    if (e < NEDGES) {
        int dst = edge_dst[e];
        int pos = g_rowptr[dst] + atomicAdd(&g_fill[dst], 1);
        g_col[pos] = edge_src[e];
    }
}

// ---------------- conversions --------------------------------------------------
__device__ __forceinline__ void split_store4(__nv_bfloat16* hi, __nv_bfloat16* lo,
                                             size_t off, float4 v) {
    __nv_bfloat16 hx = __float2bfloat16(v.x), hy = __float2bfloat16(v.y);
    __nv_bfloat16 hz = __float2bfloat16(v.z), hw = __float2bfloat16(v.w);
    __nv_bfloat162 h0; h0.x = hx; h0.y = hy;
    __nv_bfloat162 h1; h1.x = hz; h1.y = hw;
    __nv_bfloat162 l0, l1;
    l0.x = __float2bfloat16(v.x - __bfloat162float(hx));
    l0.y = __float2bfloat16(v.y - __bfloat162float(hy));
    l1.x = __float2bfloat16(v.z - __bfloat162float(hz));
    l1.y = __float2bfloat16(v.w - __bfloat162float(hw));
    *reinterpret_cast<__nv_bfloat162*>(hi + off)     = h0;
    *reinterpret_cast<__nv_bfloat162*>(hi + off + 2) = h1;
    *reinterpret_cast<__nv_bfloat162*>(lo + off)     = l0;
    *reinterpret_cast<__nv_bfloat162*>(lo + off + 2) = l1;
}

__device__ __forceinline__ void split_store2(__nv_bfloat16* hi, __nv_bfloat16* lo,
                                             size_t off, float a, float b) {
    __nv_bfloat16 ha = __float2bfloat16(a), hb = __float2bfloat16(b);
    __nv_bfloat162 h; h.x = ha; h.y = hb;
    __nv_bfloat162 l;
    l.x = __float2bfloat16(a - __bfloat162float(ha));
    l.y = __float2bfloat16(b - __bfloat162float(hb));
    *reinterpret_cast<__nv_bfloat162*>(hi + off) = h;
    *reinterpret_cast<__nv_bfloat162*>(lo + off) = l;
}

__global__ void zero_pad_kernel() {
    int row = NNODES + blockIdx.x;          // 88 blocks
    int t = threadIdx.x;
    size_t off = (size_t)row * KDUAL + t * 8;
    uint4 z = make_uint4(0, 0, 0, 0);
    *reinterpret_cast<uint4*>(g_A0hi + off) = z;
    *reinterpret_cast<uint4*>(g_A0lo + off) = z;
    *reinterpret_cast<uint4*>(g_A1hi + off) = z;
    *reinterpret_cast<uint4*>(g_A1lo + off) = z;
}

__global__ __launch_bounds__(256) void convertX_kernel(const float* __restrict__ x) {
    int row = blockIdx.x, t = threadIdx.x;
    float4 v = ((const float4*)(x + (size_t)row * DIM))[t];
    split_store4(g_A0hi, g_A0lo, (size_t)row * KDUAL + t * 4, v);
}

__global__ void transposeW_kernel(const float* __restrict__ W, int koff) {
    __shared__ float tile[32][33];
    int tx = threadIdx.x, ty = threadIdx.y;       // (32, 8)
    int nb = blockIdx.x * 32, kb = blockIdx.y * 32;
    #pragma unroll
    for (int i = 0; i < 32; i += 8)
        tile[ty + i][tx] = W[(size_t)(kb + ty + i) * DIM + nb + tx];
    __syncthreads();
    #pragma unroll
    for (int i = 0; i < 32; i += 8) {
        float v = tile[tx][ty + i];
        __nv_bfloat16 h = __float2bfloat16(v);
        size_t off = (size_t)(nb + ty + i) * KDUAL + koff + kb + tx;
        g_Bhi[off] = h;
        g_Blo[off] = __float2bfloat16(v - __bfloat162float(h));
    }
}

// ---------------- aggregation ---------------------------------------------------
// layer 0: gather fp32 x -> split into A0 cols [1024,2048)
__global__ __launch_bounds__(256)
void aggregate_f32_kernel(const float* __restrict__ feat,
                          __nv_bfloat16* __restrict__ ahi,
                          __nv_bfloat16* __restrict__ alo) {
    const int node = blockIdx.x;
    const int tid  = threadIdx.x;
    const int beg = g_rowptr[node];
    const int end = g_rowptr[node + 1];
    float4 acc0 = make_float4(0.f, 0.f, 0.f, 0.f);
    float4 acc1 = make_float4(0.f, 0.f, 0.f, 0.f);
    int i = beg;
    for (; i + 1 < end; i += 2) {
        int s0 = g_col[i], s1 = g_col[i + 1];
        float4 v0 = ((const float4*)(feat + (size_t)s0 * DIM))[tid];
        float4 v1 = ((const float4*)(feat + (size_t)s1 * DIM))[tid];
        acc0.x += v0.x; acc0.y += v0.y; acc0.z += v0.z; acc0.w += v0.w;
        acc1.x += v1.x; acc1.y += v1.y; acc1.z += v1.z; acc1.w += v1.w;
    }
    if (i < end) {
        int s0 = g_col[i];
        float4 v0 = ((const float4*)(feat + (size_t)s0 * DIM))[tid];
        acc0.x += v0.x; acc0.y += v0.y; acc0.z += v0.z; acc0.w += v0.w;
    }
    float di = g_deginv[node];
    acc0.x = (acc0.x + acc1.x) * di;
    acc0.y = (acc0.y + acc1.y) * di;
    acc0.z = (acc0.z + acc1.z) * di;
    acc0.w = (acc0.w + acc1.w) * di;
    split_store4(ahi, alo, (size_t)node * KDUAL + DIM + tid * 4, acc0);
}

// layer 1: gather hi/lo split of h (A1 cols [0,1024)), reconstruct, mean,
// split into A1 cols [1024,2048)
__global__ __launch_bounds__(256)
void aggregate_split_kernel(const __nv_bfloat16* __restrict__ fhi,
                            const __nv_bfloat16* __restrict__ flo,
                            __nv_bfloat16* __restrict__ ahi,
                            __nv_bfloat16* __restrict__ alo) {
    const int node = blockIdx.x;
    const int tid  = threadIdx.x;
    const int beg = g_rowptr[node];
    const int end = g_rowptr[node + 1];
    float4 acc = make_float4(0.f, 0.f, 0.f, 0.f);
    for (int i = beg; i < end; ++i) {
        int src = g_col[i];
        size_t off = (size_t)src * KDUAL + tid * 4;
        uint2 hraw = *reinterpret_cast<const uint2*>(fhi + off);
        uint2 lraw = *reinterpret_cast<const uint2*>(flo + off);
        __nv_bfloat162 h0 = *reinterpret_cast<__nv_bfloat162*>(&hraw.x);
        __nv_bfloat162 h1 = *reinterpret_cast<__nv_bfloat162*>(&hraw.y);
        __nv_bfloat162 l0 = *reinterpret_cast<__nv_bfloat162*>(&lraw.x);
        __nv_bfloat162 l1 = *reinterpret_cast<__nv_bfloat162*>(&lraw.y);
        acc.x += __bfloat162float(h0.x) + __bfloat162float(l0.x);
        acc.y += __bfloat162float(h0.y) + __bfloat162float(l0.y);
        acc.z += __bfloat162float(h1.x) + __bfloat162float(l1.x);
        acc.w += __bfloat162float(h1.y) + __bfloat162float(l1.y);
    }
    float di = g_deginv[node];
    acc.x *= di; acc.y *= di; acc.z *= di; acc.w *= di;
    split_store4(ahi, alo, (size_t)node * KDUAL + DIM + tid * 4, acc);
}

// ---------------- mma.sync bf16 GEMM, CTA 256x128, warp 64x64, BK=64 ------------
__global__ __launch_bounds__(256, 1)
void gemm_mma_kernel(const __nv_bfloat16* __restrict__ Ahi,
                     const __nv_bfloat16* __restrict__ Alo,
                     const float* __restrict__ bias,
                     float* __restrict__ C,
                     __nv_bfloat16* __restrict__ OutHi,
                     __nv_bfloat16* __restrict__ OutLo,
                     int M, int relu) {
    extern __shared__ __align__(1024) char smem_raw[];
    const uint32_t base = (smem_u32_of(smem_raw) + 1023u) & ~1023u;

    const int t = threadIdx.x;
    const int lane = t & 31;
    const int w = t >> 5;
    const int wm = w >> 1;            // 0..3 -> M offset wm*64
    const int wn = w & 1;             // 0..1 -> N offset wn*64
    const int m0 = blockIdx.y * 256;
    const int n0 = blockIdx.x * 128;

    const char* pAhi = (const char*)Ahi + (size_t)m0 * 4096;
    const char* pAlo = (const char*)Alo + (size_t)m0 * 4096;
    const char* pBhi = (const char*)g_Bhi + (size_t)n0 * 4096;
    const char* pBlo = (const char*)g_Blo + (size_t)n0 * 4096;

    float acc[4][8][4];
    #pragma unroll
    for (int i = 0; i < 4; ++i)
        #pragma unroll
        for (int j = 0; j < 8; ++j)
            #pragma unroll
            for (int r = 0; r < 4; ++r) acc[i][j][r] = 0.f;

    const int rowA = lane & 15;
    const int csA  = lane >> 4;
    const int rowB = (lane & 7) | ((lane & 16) >> 1);
    const int csB  = (lane >> 3) & 1;

    // stage layout: Ahi @0 (32K), Alo @32K, Bhi @64K (16K), Blo @80K
    auto load_stage = [&](int s) {
        uint32_t sb = base + (s & 1) * STAGE_BYTES;
        size_t kb = (size_t)s * 128;          // BK*2 bytes along K
        // A tiles: 256 rows x 8 chunks
        #pragma unroll
        for (int i = 0; i < 8; ++i) {
            int c = t + i * 256;
            int row = c >> 3, col = (c & 7) * 16;
            uint32_t so = sw128((uint32_t)(row * 128 + col));
            size_t go = (size_t)row * 4096 + col + kb;
            cp_async16(sb + so,         pAhi + go);
            cp_async16(sb + 32768 + so, pAlo + go);
        }
        // B tiles: 128 rows x 8 chunks
        #pragma unroll
        for (int i = 0; i < 4; ++i) {
            int c = t + i * 256;
            int row = c >> 3, col = (c & 7) * 16;
            uint32_t so = sw128((uint32_t)(row * 128 + col));
            size_t go = (size_t)row * 4096 + col + kb;
            cp_async16(sb + 65536 + so, pBhi + go);
            cp_async16(sb + 81920 + so, pBlo + go);
        }
        asm volatile("cp.async.commit_group;" ::: "memory");
    };

    load_stage(0);

    #pragma unroll 1
    for (int s = 0; s < NSTAGE; ++s) {
        if (s + 1 < NSTAGE) {
            load_stage(s + 1);
            asm volatile("cp.async.wait_group 1;" ::: "memory");
        } else {
            asm volatile("cp.async.wait_group 0;" ::: "memory");
        }
        __syncthreads();

        uint32_t sb = base + (s & 1) * STAGE_BYTES;
        const uint32_t sAhi = sb, sAlo = sb + 32768;
        const uint32_t sBhi = sb + 65536, sBlo = sb + 81920;

        #pragma unroll
        for (int kk = 0; kk < 4; ++kk) {
            uint32_t ah[4][4], al[4][4];
            #pragma unroll
            for (int mf = 0; mf < 4; ++mf) {
                int row = wm * 64 + mf * 16 + rowA;
                uint32_t off = sw128((uint32_t)(row * 128 + (kk * 2 + csA) * 16));
                ldsm_x4(ah[mf], sAhi + off);
                ldsm_x4(al[mf], sAlo + off);
            }
            #pragma unroll
            for (int nh = 0; nh < 4; ++nh) {
                int row = wn * 64 + nh * 16 + rowB;
                uint32_t off = sw128((uint32_t)(row * 128 + (kk * 2 + csB) * 16));
                uint32_t rh[4], rl[4];
                ldsm_x4(rh, sBhi + off);
                ldsm_x4(rl, sBlo + off);
                #pragma unroll
                for (int mf = 0; mf < 4; ++mf) {
                    mma_bf16(acc[mf][nh * 2],     ah[mf], rh);
                    mma_bf16(acc[mf][nh * 2],     al[mf], rh);
                    mma_bf16(acc[mf][nh * 2],     ah[mf], rl);
                    mma_bf16(acc[mf][nh * 2 + 1], ah[mf], rh + 2);
                    mma_bf16(acc[mf][nh * 2 + 1], al[mf], rh + 2);
                    mma_bf16(acc[mf][nh * 2 + 1], ah[mf], rl + 2);
                }
            }
        }
        __syncthreads();
    }

    // ---------------- epilogue ----------------
    const int r_in = lane >> 2;
    const int c_in = (lane & 3) * 2;
    #pragma unroll
    for (int mf = 0; mf < 4; ++mf) {
        int mA = m0 + wm * 64 + mf * 16 + r_in;
        int mB = mA + 8;
        #pragma unroll
        for (int nf = 0; nf < 8; ++nf) {
            int n = n0 + wn * 64 + nf * 8 + c_in;
            float bx = bias[n], by = bias[n + 1];
            float v0 = acc[mf][nf][0] + bx, v1 = acc[mf][nf][1] + by;
            float v2 = acc[mf][nf][2] + bx, v3 = acc[mf][nf][3] + by;
            if (relu) {
                v0 = fmaxf(v0, 0.f); v1 = fmaxf(v1, 0.f);
                v2 = fmaxf(v2, 0.f); v3 = fmaxf(v3, 0.f);
            }
            if (mA < M) {
                if (C) *(float2*)(C + (size_t)mA * DIM + n) = make_float2(v0, v1);
                if (OutHi) split_store2(OutHi, OutLo, (size_t)mA * KDUAL + n, v0, v1);
            }
            if (mB < M) {
                if (C) *(float2*)(C + (size_t)mB * DIM + n) = make_float2(v2, v3);
                if (OutHi) split_store2(OutHi, OutLo, (size_t)mB * KDUAL + n, v2, v3);
            }
        }
    }
}

// ---------------- launch --------------------------------------------------------
extern "C" void kernel_launch(void* const* d_in, const int* in_sizes, int n_in,
                              void* d_out, int out_size) {
    const float* x    = (const float*)d_in[0];
    const int*   esrc = (const int*)d_in[1];
    const int*   edst = (const int*)d_in[2];
    const float* Ws0  = (const float*)d_in[3];
    const float* Wn0  = (const float*)d_in[4];
    const float* b0   = (const float*)d_in[5];
    const float* Ws1  = (const float*)d_in[6];
    const float* Wn1  = (const float*)d_in[7];
    const float* b1   = (const float*)d_in[8];
    float* out = (float*)d_out;

    __nv_bfloat16 *a0h, *a0l, *a1h, *a1l;
    cudaGetSymbolAddress((void**)&a0h, g_A0hi);
    cudaGetSymbolAddress((void**)&a0l, g_A0lo);
    cudaGetSymbolAddress((void**)&a1h, g_A1hi);
    cudaGetSymbolAddress((void**)&a1l, g_A1lo);

    cudaFuncSetAttribute(gemm_mma_kernel,
                         cudaFuncAttributeMaxDynamicSharedMemorySize, SMEMSZ);

    // CSR
    zero_deg_kernel<<<(NNODES + 255) / 256, 256>>>();
    count_deg_kernel<<<(NEDGES + 255) / 256, 256>>>(edst);
    build_rowptr_kernel<<<1, 1024>>>();
    fill_csr_kernel<<<(NEDGES + 255) / 256, 256>>>(esrc, edst);

    // conversions (all weight transposes up front, off the critical path)
    zero_pad_kernel<<<MPAD - NNODES, 256>>>();
    convertX_kernel<<<NNODES, 256>>>(x);
    dim3 tgrid(32, 32), tblk(32, 8);
    transposeW_kernel<<<tgrid, tblk>>>(Ws0, 0);
    transposeW_kernel<<<tgrid, tblk>>>(Wn0, DIM);

    dim3 ggrid(DIM / 128, MPAD / 256);   // (8, 98)

    // layer 0: split(h) -> A1 cols [0,1024); no fp32 h materialized
    aggregate_f32_kernel<<<NNODES, 256>>>(x, a0h, a0l);
    gemm_mma_kernel<<<ggrid, 256, SMEMSZ>>>(a0h, a0l, b0, nullptr, a1h, a1l, NNODES, 1);

    // layer 1 weight transposes (independent of layer 0 results)
    transposeW_kernel<<<tgrid, tblk>>>(Ws1, 0);
    transposeW_kernel<<<tgrid, tblk>>>(Wn1, DIM);

    // layer 1
    aggregate_split_kernel<<<NNODES, 256>>>(a1h, a1l, a1h, a1l);
    gemm_mma_kernel<<<ggrid, 256, SMEMSZ>>>(a1h, a1l, b1, out, nullptr, nullptr, NNODES, 0);
}

// round 10
// speedup vs baseline: 1.1723x; 1.1723x over previous
#include <cuda_runtime.h>
#include <cuda_fp16.h>
#include <cstdint>

#define NNODES 25000
#define NEDGES 400000
#define DIM    1024
#define MPAD   25088          // 196 * 128
#define KDUAL  2048
#define BK     32
#define NSTAGE (KDUAL / BK)   // 64
#define NBUF   4
#define STAGE_BYTES 24576     // Ahi 8K + Alo 8K + Bhi 8K
#define SMEMSZ (NBUF * STAGE_BYTES + 1024)

// ---------------- device scratch ---------------------------------------------
__device__ int   g_deg[NNODES];
__device__ float g_deginv[NNODES];
__device__ int   g_rowptr[NNODES + 1];
__device__ int   g_fill[NNODES];
__device__ int   g_col[NEDGES];
__device__ __align__(256) __half g_A0hi[(size_t)MPAD * KDUAL];
__device__ __align__(256) __half g_A0lo[(size_t)MPAD * KDUAL];
__device__ __align__(256) __half g_A1hi[(size_t)MPAD * KDUAL];
__device__ __align__(256) __half g_A1lo[(size_t)MPAD * KDUAL];
__device__ __align__(256) __half g_Bhi[(size_t)DIM * KDUAL];   // [N][K] = fp16(W^T)

// ---------------- helpers ------------------------------------------------------
__device__ __forceinline__ uint32_t smem_u32_of(const void* p) {
    uint32_t a;
    asm("{ .reg .u64 t; cvta.to.shared.u64 t, %1; cvt.u32.u64 %0, t; }" : "=r"(a) : "l"(p));
    return a;
}

__device__ __forceinline__ uint32_t sw128(uint32_t off) {
    return off ^ ((off >> 3) & 0x70);
}

__device__ __forceinline__ void cp_async16(uint32_t saddr, const void* g) {
    asm volatile("cp.async.cg.shared.global [%0], [%1], 16;" :: "r"(saddr), "l"(g));
}

__device__ __forceinline__ void ldsm_x4(uint32_t* r, uint32_t addr) {
    asm volatile("ldmatrix.sync.aligned.m8n8.x4.shared.b16 {%0,%1,%2,%3}, [%4];"
                 : "=r"(r[0]), "=r"(r[1]), "=r"(r[2]), "=r"(r[3]) : "r"(addr));
}

__device__ __forceinline__ void mma_f16(float* d, const uint32_t* a, const uint32_t* b) {
    asm volatile(
        "mma.sync.aligned.m16n8k16.row.col.f32.f16.f16.f32 "
        "{%0,%1,%2,%3}, {%4,%5,%6,%7}, {%8,%9}, {%0,%1,%2,%3};"
        : "+f"(d[0]), "+f"(d[1]), "+f"(d[2]), "+f"(d[3])
        : "r"(a[0]), "r"(a[1]), "r"(a[2]), "r"(a[3]), "r"(b[0]), "r"(b[1]));
}

// ---------------- CSR build ---------------------------------------------------
__global__ void zero_deg_kernel() {
    int i = blockIdx.x * blockDim.x + threadIdx.x;
    if (i < NNODES) g_deg[i] = 0;
}

__global__ void count_deg_kernel(const int* __restrict__ edge_dst) {
    int e = blockIdx.x * blockDim.x + threadIdx.x;
    if (e < NEDGES) atomicAdd(&g_deg[edge_dst[e]], 1);
}

__global__ void build_rowptr_kernel() {
    __shared__ int sums[1024];
    const int tid = threadIdx.x;
    const int CHUNK = 25;
    const int start = tid * CHUNK;
    int s = 0;
    for (int i = 0; i < CHUNK; ++i) {
        int idx = start + i;
        if (idx < NNODES) s += g_deg[idx];
    }
    sums[tid] = s;
    __syncthreads();
    for (int off = 1; off < 1024; off <<= 1) {
        int add = 0;
        if (tid >= off) add = sums[tid - off];
        __syncthreads();
        sums[tid] += add;
        __syncthreads();
    }
    int prefix = (tid > 0) ? sums[tid - 1] : 0;
    for (int i = 0; i < CHUNK; ++i) {
        int idx = start + i;
        if (idx < NNODES) {
            g_rowptr[idx] = prefix;
            int d = g_deg[idx];
            prefix += d;
            g_deginv[idx] = 1.0f / fmaxf((float)d, 1.0f);
            g_fill[idx] = 0;
        }
    }
    if (tid == 1023) g_rowptr[NNODES] = sums[1023];
}

__global__ void fill_csr_kernel(const int* __restrict__ edge_src,
                                const int* __restrict__ edge_dst) {
    int e = blockIdx.x * blockDim.x + threadIdx.x;
    if (e < NEDGES) {
        int dst = edge_dst[e];
        int pos = g_rowptr[dst] + atomicAdd(&g_fill[dst], 1);
        g_col[pos] = edge_src[e];
    }
}

// ---------------- conversions --------------------------------------------------
__device__ __forceinline__ void split_store4(__half* hi, __half* lo,
                                             size_t off, float4 v) {
    __half hx = __float2half_rn(v.x), hy = __float2half_rn(v.y);
    __half hz = __float2half_rn(v.z), hw = __float2half_rn(v.w);
    __half2 h0; h0.x = hx; h0.y = hy;
    __half2 h1; h1.x = hz; h1.y = hw;
    __half2 l0, l1;
    l0.x = __float2half_rn(v.x - __half2float(hx));
    l0.y = __float2half_rn(v.y - __half2float(hy));
    l1.x = __float2half_rn(v.z - __half2float(hz));
    l1.y = __float2half_rn(v.w - __half2float(hw));
    *reinterpret_cast<__half2*>(hi + off)     = h0;
    *reinterpret_cast<__half2*>(hi + off + 2) = h1;
    *reinterpret_cast<__half2*>(lo + off)     = l0;
    *reinterpret_cast<__half2*>(lo + off + 2) = l1;
}

__device__ __forceinline__ void split_store2(__half* hi, __half* lo,
                                             size_t off, float a, float b) {
    __half ha = __float2half_rn(a), hb = __float2half_rn(b);
    __half2 h; h.x = ha; h.y = hb;
    __half2 l;
    l.x = __float2half_rn(a - __half2float(ha));
    l.y = __float2half_rn(b - __half2float(hb));
    *reinterpret_cast<__half2*>(hi + off) = h;
    *reinterpret_cast<__half2*>(lo + off) = l;
}

__global__ void zero_pad_kernel() {
    int row = NNODES + blockIdx.x;          // 88 blocks
    int t = threadIdx.x;
    size_t off = (size_t)row * KDUAL + t * 8;
    uint4 z = make_uint4(0, 0, 0, 0);
    *reinterpret_cast<uint4*>(g_A0hi + off) = z;
    *reinterpret_cast<uint4*>(g_A0lo + off) = z;
    *reinterpret_cast<uint4*>(g_A1hi + off) = z;
    *reinterpret_cast<uint4*>(g_A1lo + off) = z;
}

__global__ __launch_bounds__(256) void convertX_kernel(const float* __restrict__ x) {
    int row = blockIdx.x, t = threadIdx.x;
    float4 v = ((const float4*)(x + (size_t)row * DIM))[t];
    split_store4(g_A0hi, g_A0lo, (size_t)row * KDUAL + t * 4, v);
}

// W[k][n] fp32 -> B^T[n][koff+k] fp16 (hi only)
__global__ void transposeW_kernel(const float* __restrict__ W, int koff) {
    __shared__ float tile[32][33];
    int tx = threadIdx.x, ty = threadIdx.y;       // (32, 8)
    int nb = blockIdx.x * 32, kb = blockIdx.y * 32;
    #pragma unroll
    for (int i = 0; i < 32; i += 8)
        tile[ty + i][tx] = W[(size_t)(kb + ty + i) * DIM + nb + tx];
    __syncthreads();
    #pragma unroll
    for (int i = 0; i < 32; i += 8) {
        float v = tile[tx][ty + i];
        g_Bhi[(size_t)(nb + ty + i) * KDUAL + koff + kb + tx] = __float2half_rn(v);
    }
}

// ---------------- aggregation ---------------------------------------------------
// layer 0: gather fp32 x -> split into A0 cols [1024,2048)
__global__ __launch_bounds__(256)
void aggregate_f32_kernel(const float* __restrict__ feat,
                          __half* __restrict__ ahi,
                          __half* __restrict__ alo) {
    const int node = blockIdx.x;
    const int tid  = threadIdx.x;
    const int beg = g_rowptr[node];
    const int end = g_rowptr[node + 1];
    float4 acc0 = make_float4(0.f, 0.f, 0.f, 0.f);
    float4 acc1 = make_float4(0.f, 0.f, 0.f, 0.f);
    int i = beg;
    for (; i + 1 < end; i += 2) {
        int s0 = g_col[i], s1 = g_col[i + 1];
        float4 v0 = ((const float4*)(feat + (size_t)s0 * DIM))[tid];
        float4 v1 = ((const float4*)(feat + (size_t)s1 * DIM))[tid];
        acc0.x += v0.x; acc0.y += v0.y; acc0.z += v0.z; acc0.w += v0.w;
        acc1.x += v1.x; acc1.y += v1.y; acc1.z += v1.z; acc1.w += v1.w;
    }
    if (i < end) {
        int s0 = g_col[i];
        float4 v0 = ((const float4*)(feat + (size_t)s0 * DIM))[tid];
        acc0.x += v0.x; acc0.y += v0.y; acc0.z += v0.z; acc0.w += v0.w;
    }
    float di = g_deginv[node];
    acc0.x = (acc0.x + acc1.x) * di;
    acc0.y = (acc0.y + acc1.y) * di;
    acc0.z = (acc0.z + acc1.z) * di;
    acc0.w = (acc0.w + acc1.w) * di;
    split_store4(ahi, alo, (size_t)node * KDUAL + DIM + tid * 4, acc0);
}

// layer 1: gather fp16 hi/lo of h (A1 cols [0,1024)), reconstruct, mean,
// split into A1 cols [1024,2048)
__global__ __launch_bounds__(256)
void aggregate_split_kernel(const __half* __restrict__ fhi,
                            const __half* __restrict__ flo,
                            __half* __restrict__ ahi,
                            __half* __restrict__ alo) {
    const int node = blockIdx.x;
    const int tid  = threadIdx.x;
    const int beg = g_rowptr[node];
    const int end = g_rowptr[node + 1];
    float4 acc = make_float4(0.f, 0.f, 0.f, 0.f);
    for (int i = beg; i < end; ++i) {
        int src = g_col[i];
        size_t off = (size_t)src * KDUAL + tid * 4;
        uint2 hraw = *reinterpret_cast<const uint2*>(fhi + off);
        uint2 lraw = *reinterpret_cast<const uint2*>(flo + off);
        __half2 h0 = *reinterpret_cast<__half2*>(&hraw.x);
        __half2 h1 = *reinterpret_cast<__half2*>(&hraw.y);
        __half2 l0 = *reinterpret_cast<__half2*>(&lraw.x);
        __half2 l1 = *reinterpret_cast<__half2*>(&lraw.y);
        acc.x += __half2float(h0.x) + __half2float(l0.x);
        acc.y += __half2float(h0.y) + __half2float(l0.y);
        acc.z += __half2float(h1.x) + __half2float(l1.x);
        acc.w += __half2float(h1.y) + __half2float(l1.y);
    }
    float di = g_deginv[node];
    acc.x *= di; acc.y *= di; acc.z *= di; acc.w *= di;
    split_store4(ahi, alo, (size_t)node * KDUAL + DIM + tid * 4, acc);
}

// ---------------- mma.sync fp16 GEMM (2-product split) ---------------------------
// C[M,1024] = (Ahi+Alo) @ Bhi^T + bias; 128x128 CTA, BK=32, 4-stage, 8 warps 64x32.
__global__ __launch_bounds__(256)
void gemm_mma_kernel(const __half* __restrict__ Ahi,
                     const __half* __restrict__ Alo,
                     const float* __restrict__ bias,
                     float* __restrict__ C,
                     __half* __restrict__ OutHi,
                     __half* __restrict__ OutLo,
                     int M, int relu) {
    extern __shared__ __align__(1024) char smem_raw[];
    const uint32_t base = (smem_u32_of(smem_raw) + 1023u) & ~1023u;

    const int t = threadIdx.x;
    const int lane = t & 31;
    const int w = t >> 5;
    const int wm = w >> 2;            // 0..1 -> M offset wm*64
    const int wn = w & 3;             // 0..3 -> N offset wn*32
    const int m0 = blockIdx.y * 128;
    const int n0 = blockIdx.x * 128;

    const char* pAhi = (const char*)Ahi + (size_t)m0 * 4096;
    const char* pAlo = (const char*)Alo + (size_t)m0 * 4096;
    const char* pBhi = (const char*)g_Bhi + (size_t)n0 * 4096;

    float acc[4][4][4];
    #pragma unroll
    for (int i = 0; i < 4; ++i)
        #pragma unroll
        for (int j = 0; j < 4; ++j)
            #pragma unroll
            for (int r = 0; r < 4; ++r) acc[i][j][r] = 0.f;

    const int rowA = lane & 15;
    const int csA  = lane >> 4;
    const int rowB = (lane & 7) | ((lane & 16) >> 1);
    const int csB  = (lane >> 3) & 1;

    // stage layout: Ahi @0, Alo @8192, Bhi @16384 (each 128 rows x 64B, SW128)
    auto load_stage = [&](int s) {
        uint32_t sb = base + (s & (NBUF - 1)) * STAGE_BYTES;
        size_t kb = (size_t)s * 64;           // BK*2 bytes along K
        const char* srcs[3] = { pAhi + kb, pAlo + kb, pBhi + kb };
        #pragma unroll
        for (int tile = 0; tile < 3; ++tile) {
            uint32_t tb = sb + tile * 8192;
            const char* g = srcs[tile];
            #pragma unroll
            for (int i = 0; i < 2; ++i) {
                int chunk = t + i * 256;      // 512 chunks of 16B per tile
                int row = chunk >> 2;
                int c   = chunk & 3;
                cp_async16(tb + sw128((uint32_t)(row * 64 + c * 16)),
                           g + (size_t)row * 4096 + c * 16);
            }
        }
        asm volatile("cp.async.commit_group;" ::: "memory");
    };

    load_stage(0);
    load_stage(1);
    load_stage(2);

    #pragma unroll 1
    for (int s = 0; s < NSTAGE; ++s) {
        if (s < NSTAGE - 2)
            asm volatile("cp.async.wait_group 2;" ::: "memory");
        else if (s < NSTAGE - 1)
            asm volatile("cp.async.wait_group 1;" ::: "memory");
        else
            asm volatile("cp.async.wait_group 0;" ::: "memory");
        __syncthreads();                      // single barrier per stage (NBUF=4)

        if (s + 3 < NSTAGE) load_stage(s + 3);

        uint32_t sb = base + (s & (NBUF - 1)) * STAGE_BYTES;
        const uint32_t sAhi = sb, sAlo = sb + 8192, sBhi = sb + 16384;

        #pragma unroll
        for (int kk = 0; kk < 2; ++kk) {
            uint32_t ah[4][4], al[4][4];
            #pragma unroll
            for (int mf = 0; mf < 4; ++mf) {
                int row = wm * 64 + mf * 16 + rowA;
                uint32_t off = sw128((uint32_t)(row * 64 + (kk * 2 + csA) * 16));
                ldsm_x4(ah[mf], sAhi + off);
                ldsm_x4(al[mf], sAlo + off);
            }
            #pragma unroll
            for (int nh = 0; nh < 2; ++nh) {
                int row = wn * 32 + nh * 16 + rowB;
                uint32_t off = sw128((uint32_t)(row * 64 + (kk * 2 + csB) * 16));
                uint32_t rh[4];
                ldsm_x4(rh, sBhi + off);
                #pragma unroll
                for (int mf = 0; mf < 4; ++mf) {
                    mma_f16(acc[mf][nh * 2],     ah[mf], rh);
                    mma_f16(acc[mf][nh * 2],     al[mf], rh);
                    mma_f16(acc[mf][nh * 2 + 1], ah[mf], rh + 2);
                    mma_f16(acc[mf][nh * 2 + 1], al[mf], rh + 2);
                }
            }
        }
    }

    // ---------------- epilogue ----------------
    const int r_in = lane >> 2;
    const int c_in = (lane & 3) * 2;
    #pragma unroll
    for (int mf = 0; mf < 4; ++mf) {
        int mA = m0 + wm * 64 + mf * 16 + r_in;
        int mB = mA + 8;
        #pragma unroll
        for (int nf = 0; nf < 4; ++nf) {
            int n = n0 + wn * 32 + nf * 8 + c_in;
            float bx = bias[n], by = bias[n + 1];
            float v0 = acc[mf][nf][0] + bx, v1 = acc[mf][nf][1] + by;
            float v2 = acc[mf][nf][2] + bx, v3 = acc[mf][nf][3] + by;
            if (relu) {
                v0 = fmaxf(v0, 0.f); v1 = fmaxf(v1, 0.f);
                v2 = fmaxf(v2, 0.f); v3 = fmaxf(v3, 0.f);
            }
            if (mA < M) {
                if (C) *(float2*)(C + (size_t)mA * DIM + n) = make_float2(v0, v1);
                if (OutHi) split_store2(OutHi, OutLo, (size_t)mA * KDUAL + n, v0, v1);
            }
            if (mB < M) {
                if (C) *(float2*)(C + (size_t)mB * DIM + n) = make_float2(v2, v3);
                if (OutHi) split_store2(OutHi, OutLo, (size_t)mB * KDUAL + n, v2, v3);
            }
        }
    }
}

// ---------------- launch --------------------------------------------------------
extern "C" void kernel_launch(void* const* d_in, const int* in_sizes, int n_in,
                              void* d_out, int out_size) {
    const float* x    = (const float*)d_in[0];
    const int*   esrc = (const int*)d_in[1];
    const int*   edst = (const int*)d_in[2];
    const float* Ws0  = (const float*)d_in[3];
    const float* Wn0  = (const float*)d_in[4];
    const float* b0   = (const float*)d_in[5];
    const float* Ws1  = (const float*)d_in[6];
    const float* Wn1  = (const float*)d_in[7];
    const float* b1   = (const float*)d_in[8];
    float* out = (float*)d_out;

    __half *a0h, *a0l, *a1h, *a1l;
    cudaGetSymbolAddress((void**)&a0h, g_A0hi);
    cudaGetSymbolAddress((void**)&a0l, g_A0lo);
    cudaGetSymbolAddress((void**)&a1h, g_A1hi);
    cudaGetSymbolAddress((void**)&a1l, g_A1lo);

    cudaFuncSetAttribute(gemm_mma_kernel,
                         cudaFuncAttributeMaxDynamicSharedMemorySize, SMEMSZ);

    // CSR
    zero_deg_kernel<<<(NNODES + 255) / 256, 256>>>();
    count_deg_kernel<<<(NEDGES + 255) / 256, 256>>>(edst);
    build_rowptr_kernel<<<1, 1024>>>();
    fill_csr_kernel<<<(NEDGES + 255) / 256, 256>>>(esrc, edst);

    // conversions
    zero_pad_kernel<<<MPAD - NNODES, 256>>>();
    convertX_kernel<<<NNODES, 256>>>(x);
    dim3 tgrid(32, 32), tblk(32, 8);
    transposeW_kernel<<<tgrid, tblk>>>(Ws0, 0);
    transposeW_kernel<<<tgrid, tblk>>>(Wn0, DIM);

    dim3 ggrid(DIM / 128, MPAD / 128);   // (8, 196)

    // layer 0: split(h) -> A1 cols [0,1024); no fp32 h materialized
    aggregate_f32_kernel<<<NNODES, 256>>>(x, a0h, a0l);
    gemm_mma_kernel<<<ggrid, 256, SMEMSZ>>>(a0h, a0l, b0, nullptr, a1h, a1l, NNODES, 1);

    // layer 1 weight transpose (independent of layer 0 results)
    transposeW_kernel<<<tgrid, tblk>>>(Ws1, 0);
    transposeW_kernel<<<tgrid, tblk>>>(Wn1, DIM);

    // layer 1
    aggregate_split_kernel<<<NNODES, 256>>>(a1h, a1l, a1h, a1l);
    gemm_mma_kernel<<<ggrid, 256, SMEMSZ>>>(a1h, a1l, b1, out, nullptr, nullptr, NNODES, 0);
}

// round 11
// speedup vs baseline: 2.3730x; 2.0243x over previous
#include <cuda_runtime.h>
#include <cuda_fp16.h>
#include <cstdint>

#define NNODES 25000
#define NEDGES 400000
#define DIM    1024
#define MPAD   25088          // 196 * 128
#define KDUAL  2048
#define BK     64
#define NSTAGE (KDUAL / BK)   // 32
#define NBUF   3
#define STAGE_BYTES 32768     // A 16K + B 16K
#define SMEMSZ (NBUF * STAGE_BYTES + 1024)

// ---------------- device scratch ---------------------------------------------
__device__ int   g_deg[NNODES];
__device__ float g_deginv[NNODES];
__device__ int   g_rowptr[NNODES + 1];
__device__ int   g_fill[NNODES];
__device__ int   g_col[NEDGES];
__device__ __align__(256) __half g_A0[(size_t)MPAD * KDUAL];   // [x | mean(x)] fp16
__device__ __align__(256) __half g_A1[(size_t)MPAD * KDUAL];   // [h | mean(h)] fp16
__device__ __align__(256) __half g_B[(size_t)DIM * KDUAL];     // [N][K] = fp16(W^T)

// ---------------- helpers ------------------------------------------------------
__device__ __forceinline__ uint32_t smem_u32_of(const void* p) {
    uint32_t a;
    asm("{ .reg .u64 t; cvta.to.shared.u64 t, %1; cvt.u32.u64 %0, t; }" : "=r"(a) : "l"(p));
    return a;
}

__device__ __forceinline__ uint32_t sw128(uint32_t off) {
    return off ^ ((off >> 3) & 0x70);
}

__device__ __forceinline__ void cp_async16(uint32_t saddr, const void* g) {
    asm volatile("cp.async.cg.shared.global [%0], [%1], 16;" :: "r"(saddr), "l"(g));
}

__device__ __forceinline__ void ldsm_x4(uint32_t* r, uint32_t addr) {
    asm volatile("ldmatrix.sync.aligned.m8n8.x4.shared.b16 {%0,%1,%2,%3}, [%4];"
                 : "=r"(r[0]), "=r"(r[1]), "=r"(r[2]), "=r"(r[3]) : "r"(addr));
}

__device__ __forceinline__ void mma_f16(float* d, const uint32_t* a, const uint32_t* b) {
    asm volatile(
        "mma.sync.aligned.m16n8k16.row.col.f32.f16.f16.f32 "
        "{%0,%1,%2,%3}, {%4,%5,%6,%7}, {%8,%9}, {%0,%1,%2,%3};"
        : "+f"(d[0]), "+f"(d[1]), "+f"(d[2]), "+f"(d[3])
        : "r"(a[0]), "r"(a[1]), "r"(a[2]), "r"(a[3]), "r"(b[0]), "r"(b[1]));
}

// ---------------- CSR build ---------------------------------------------------
__global__ void zero_deg_kernel() {
    int i = blockIdx.x * blockDim.x + threadIdx.x;
    if (i < NNODES) g_deg[i] = 0;
}

__global__ void count_deg_kernel(const int* __restrict__ edge_dst) {
    int e = blockIdx.x * blockDim.x + threadIdx.x;
    if (e < NEDGES) atomicAdd(&g_deg[edge_dst[e]], 1);
}

__global__ void build_rowptr_kernel() {
    __shared__ int sums[1024];
    const int tid = threadIdx.x;
    const int CHUNK = 25;
    const int start = tid * CHUNK;
    int s = 0;
    for (int i = 0; i < CHUNK; ++i) {
        int idx = start + i;
        if (idx < NNODES) s += g_deg[idx];
    }
    sums[tid] = s;
    __syncthreads();
    for (int off = 1; off < 1024; off <<= 1) {
        int add = 0;
        if (tid >= off) add = sums[tid - off];
        __syncthreads();
        sums[tid] += add;
        __syncthreads();
    }
    int prefix = (tid > 0) ? sums[tid - 1] : 0;
    for (int i = 0; i < CHUNK; ++i) {
        int idx = start + i;
        if (idx < NNODES) {
            g_rowptr[idx] = prefix;
            int d = g_deg[idx];
            prefix += d;
            g_deginv[idx] = 1.0f / fmaxf((float)d, 1.0f);
            g_fill[idx] = 0;
        }
    }
    if (tid == 1023) g_rowptr[NNODES] = sums[1023];
}

__global__ void fill_csr_kernel(const int* __restrict__ edge_src,
                                const int* __restrict__ edge_dst) {
    int e = blockIdx.x * blockDim.x + threadIdx.x;
    if (e < NEDGES) {
        int dst = edge_dst[e];
        int pos = g_rowptr[dst] + atomicAdd(&g_fill[dst], 1);
        g_col[pos] = edge_src[e];
    }
}

// ---------------- conversions --------------------------------------------------
__device__ __forceinline__ void store4_f16(__half* dst, size_t off, float4 v) {
    __half2 h0; h0.x = __float2half_rn(v.x); h0.y = __float2half_rn(v.y);
    __half2 h1; h1.x = __float2half_rn(v.z); h1.y = __float2half_rn(v.w);
    *reinterpret_cast<__half2*>(dst + off)     = h0;
    *reinterpret_cast<__half2*>(dst + off + 2) = h1;
}

__global__ void zero_pad_kernel() {
    int row = NNODES + blockIdx.x;          // 88 blocks
    int t = threadIdx.x;
    size_t off = (size_t)row * KDUAL + t * 8;
    uint4 z = make_uint4(0, 0, 0, 0);
    *reinterpret_cast<uint4*>(g_A0 + off) = z;
    *reinterpret_cast<uint4*>(g_A1 + off) = z;
}

__global__ __launch_bounds__(256) void convertX_kernel(const float* __restrict__ x) {
    int row = blockIdx.x, t = threadIdx.x;
    float4 v = ((const float4*)(x + (size_t)row * DIM))[t];
    store4_f16(g_A0, (size_t)row * KDUAL + t * 4, v);
}

// W[k][n] fp32 -> B^T[n][koff+k] fp16
__global__ void transposeW_kernel(const float* __restrict__ W, int koff) {
    __shared__ float tile[32][33];
    int tx = threadIdx.x, ty = threadIdx.y;       // (32, 8)
    int nb = blockIdx.x * 32, kb = blockIdx.y * 32;
    #pragma unroll
    for (int i = 0; i < 32; i += 8)
        tile[ty + i][tx] = W[(size_t)(kb + ty + i) * DIM + nb + tx];
    __syncthreads();
    #pragma unroll
    for (int i = 0; i < 32; i += 8) {
        float v = tile[tx][ty + i];
        g_B[(size_t)(nb + ty + i) * KDUAL + koff + kb + tx] = __float2half_rn(v);
    }
}

// ---------------- aggregation ---------------------------------------------------
// layer 0: gather fp32 x -> fp16 mean into A0 cols [1024,2048)
__global__ __launch_bounds__(256)
void aggregate_f32_kernel(const float* __restrict__ feat) {
    const int node = blockIdx.x;
    const int tid  = threadIdx.x;
    const int beg = g_rowptr[node];
    const int end = g_rowptr[node + 1];
    float4 acc0 = make_float4(0.f, 0.f, 0.f, 0.f);
    float4 acc1 = make_float4(0.f, 0.f, 0.f, 0.f);
    int i = beg;
    for (; i + 1 < end; i += 2) {
        int s0 = g_col[i], s1 = g_col[i + 1];
        float4 v0 = ((const float4*)(feat + (size_t)s0 * DIM))[tid];
        float4 v1 = ((const float4*)(feat + (size_t)s1 * DIM))[tid];
        acc0.x += v0.x; acc0.y += v0.y; acc0.z += v0.z; acc0.w += v0.w;
        acc1.x += v1.x; acc1.y += v1.y; acc1.z += v1.z; acc1.w += v1.w;
    }
    if (i < end) {
        int s0 = g_col[i];
        float4 v0 = ((const float4*)(feat + (size_t)s0 * DIM))[tid];
        acc0.x += v0.x; acc0.y += v0.y; acc0.z += v0.z; acc0.w += v0.w;
    }
    float di = g_deginv[node];
    acc0.x = (acc0.x + acc1.x) * di;
    acc0.y = (acc0.y + acc1.y) * di;
    acc0.z = (acc0.z + acc1.z) * di;
    acc0.w = (acc0.w + acc1.w) * di;
    store4_f16(g_A0, (size_t)node * KDUAL + DIM + tid * 4, acc0);
}

// layer 1: gather fp16 h from A1 cols [0,1024), fp32 accumulate, mean ->
// fp16 into A1 cols [1024,2048)
__global__ __launch_bounds__(256)
void aggregate_f16_kernel() {
    const int node = blockIdx.x;
    const int tid  = threadIdx.x;
    const int beg = g_rowptr[node];
    const int end = g_rowptr[node + 1];
    float4 acc0 = make_float4(0.f, 0.f, 0.f, 0.f);
    float4 acc1 = make_float4(0.f, 0.f, 0.f, 0.f);
    int i = beg;
    for (; i + 1 < end; i += 2) {
        int s0 = g_col[i], s1 = g_col[i + 1];
        uint2 r0 = *reinterpret_cast<const uint2*>(g_A1 + (size_t)s0 * KDUAL + tid * 4);
        uint2 r1 = *reinterpret_cast<const uint2*>(g_A1 + (size_t)s1 * KDUAL + tid * 4);
        float2 a0 = __half22float2(*reinterpret_cast<__half2*>(&r0.x));
        float2 b0 = __half22float2(*reinterpret_cast<__half2*>(&r0.y));
        float2 a1 = __half22float2(*reinterpret_cast<__half2*>(&r1.x));
        float2 b1 = __half22float2(*reinterpret_cast<__half2*>(&r1.y));
        acc0.x += a0.x; acc0.y += a0.y; acc0.z += b0.x; acc0.w += b0.y;
        acc1.x += a1.x; acc1.y += a1.y; acc1.z += b1.x; acc1.w += b1.y;
    }
    if (i < end) {
        int s0 = g_col[i];
        uint2 r0 = *reinterpret_cast<const uint2*>(g_A1 + (size_t)s0 * KDUAL + tid * 4);
        float2 a0 = __half22float2(*reinterpret_cast<__half2*>(&r0.x));
        float2 b0 = __half22float2(*reinterpret_cast<__half2*>(&r0.y));
        acc0.x += a0.x; acc0.y += a0.y; acc0.z += b0.x; acc0.w += b0.y;
    }
    float di = g_deginv[node];
    acc0.x = (acc0.x + acc1.x) * di;
    acc0.y = (acc0.y + acc1.y) * di;
    acc0.z = (acc0.z + acc1.z) * di;
    acc0.w = (acc0.w + acc1.w) * di;
    store4_f16(g_A1, (size_t)node * KDUAL + DIM + tid * 4, acc0);
}

// ---------------- mma.sync fp16 GEMM (single product) ----------------------------
// C[M,1024] = A @ B^T + bias; 128x128 CTA tile, BK=64, 3-stage, 8 warps 64x32.
__global__ __launch_bounds__(256)
void gemm_f16_kernel(const __half* __restrict__ A,
                     const float* __restrict__ bias,
                     float* __restrict__ C,
                     __half* __restrict__ OutH,
                     int M, int relu) {
    extern __shared__ __align__(1024) char smem_raw[];
    const uint32_t base = (smem_u32_of(smem_raw) + 1023u) & ~1023u;

    const int t = threadIdx.x;
    const int lane = t & 31;
    const int w = t >> 5;
    const int wm = w >> 2;            // 0..1 -> M offset wm*64
    const int wn = w & 3;             // 0..3 -> N offset wn*32
    const int m0 = blockIdx.y * 128;
    const int n0 = blockIdx.x * 128;

    const char* pA = (const char*)A + (size_t)m0 * 4096;
    const char* pB = (const char*)g_B + (size_t)n0 * 4096;

    float acc[4][4][4];
    #pragma unroll
    for (int i = 0; i < 4; ++i)
        #pragma unroll
        for (int j = 0; j < 4; ++j)
            #pragma unroll
            for (int r = 0; r < 4; ++r) acc[i][j][r] = 0.f;

    const int rowA = lane & 15;
    const int csA  = lane >> 4;
    const int rowB = (lane & 7) | ((lane & 16) >> 1);
    const int csB  = (lane >> 3) & 1;

    // stage: A tile 128x64 fp16 (128B rows, SW128) @0, B tile @16384
    auto load_stage = [&](int s) {
        uint32_t sb = base + (s % NBUF) * STAGE_BYTES;
        size_t kb = (size_t)s * 128;          // BK*2 bytes along K
        #pragma unroll
        for (int i = 0; i < 4; ++i) {
            int c = t + i * 256;              // 1024 chunks of 16B per tile
            int row = c >> 3, col = (c & 7) * 16;
            uint32_t so = sw128((uint32_t)(row * 128 + col));
            size_t go = (size_t)row * 4096 + col + kb;
            cp_async16(sb + so,         pA + go);
            cp_async16(sb + 16384 + so, pB + go);
        }
        asm volatile("cp.async.commit_group;" ::: "memory");
    };

    load_stage(0);
    load_stage(1);

    #pragma unroll 1
    for (int s = 0; s < NSTAGE; ++s) {
        if (s == NSTAGE - 1)
            asm volatile("cp.async.wait_group 0;" ::: "memory");
        else
            asm volatile("cp.async.wait_group 1;" ::: "memory");
        __syncthreads();
        if (s + 2 < NSTAGE) load_stage(s + 2);   // buf (s+2)%3: compute(s-1) done

        uint32_t sb = base + (s % NBUF) * STAGE_BYTES;
        const uint32_t sA = sb, sB = sb + 16384;

        #pragma unroll
        for (int kk = 0; kk < 4; ++kk) {
            uint32_t ah[4][4];
            #pragma unroll
            for (int mf = 0; mf < 4; ++mf) {
                int row = wm * 64 + mf * 16 + rowA;
                ldsm_x4(ah[mf], sA + sw128((uint32_t)(row * 128 + (kk * 2 + csA) * 16)));
            }
            #pragma unroll
            for (int nh = 0; nh < 2; ++nh) {
                int row = wn * 32 + nh * 16 + rowB;
                uint32_t rh[4];
                ldsm_x4(rh, sB + sw128((uint32_t)(row * 128 + (kk * 2 + csB) * 16)));
                #pragma unroll
                for (int mf = 0; mf < 4; ++mf) {
                    mma_f16(acc[mf][nh * 2],     ah[mf], rh);
                    mma_f16(acc[mf][nh * 2 + 1], ah[mf], rh + 2);
                }
            }
        }
        __syncthreads();
    }

    // ---------------- epilogue ----------------
    const int r_in = lane >> 2;
    const int c_in = (lane & 3) * 2;
    #pragma unroll
    for (int mf = 0; mf < 4; ++mf) {
        int mA = m0 + wm * 64 + mf * 16 + r_in;
        int mB = mA + 8;
        #pragma unroll
        for (int nf = 0; nf < 4; ++nf) {
            int n = n0 + wn * 32 + nf * 8 + c_in;
            float bx = bias[n], by = bias[n + 1];
            float v0 = acc[mf][nf][0] + bx, v1 = acc[mf][nf][1] + by;
            float v2 = acc[mf][nf][2] + bx, v3 = acc[mf][nf][3] + by;
            if (relu) {
                v0 = fmaxf(v0, 0.f); v1 = fmaxf(v1, 0.f);
                v2 = fmaxf(v2, 0.f); v3 = fmaxf(v3, 0.f);
            }
            if (mA < M) {
                if (C) *(float2*)(C + (size_t)mA * DIM + n) = make_float2(v0, v1);
                if (OutH) {
                    __half2 h; h.x = __float2half_rn(v0); h.y = __float2half_rn(v1);
                    *reinterpret_cast<__half2*>(OutH + (size_t)mA * KDUAL + n) = h;
                }
            }
            if (mB < M) {
                if (C) *(float2*)(C + (size_t)mB * DIM + n) = make_float2(v2, v3);
                if (OutH) {
                    __half2 h; h.x = __float2half_rn(v2); h.y = __float2half_rn(v3);
                    *reinterpret_cast<__half2*>(OutH + (size_t)mB * KDUAL + n) = h;
                }
            }
        }
    }
}

// ---------------- launch --------------------------------------------------------
extern "C" void kernel_launch(void* const* d_in, const int* in_sizes, int n_in,
                              void* d_out, int out_size) {
    const float* x    = (const float*)d_in[0];
    const int*   esrc = (const int*)d_in[1];
    const int*   edst = (const int*)d_in[2];
    const float* Ws0  = (const float*)d_in[3];
    const float* Wn0  = (const float*)d_in[4];
    const float* b0   = (const float*)d_in[5];
    const float* Ws1  = (const float*)d_in[6];
    const float* Wn1  = (const float*)d_in[7];
    const float* b1   = (const float*)d_in[8];
    float* out = (float*)d_out;

    __half *a0, *a1;
    cudaGetSymbolAddress((void**)&a0, g_A0);
    cudaGetSymbolAddress((void**)&a1, g_A1);

    cudaFuncSetAttribute(gemm_f16_kernel,
                         cudaFuncAttributeMaxDynamicSharedMemorySize, SMEMSZ);

    // CSR
    zero_deg_kernel<<<(NNODES + 255) / 256, 256>>>();
    count_deg_kernel<<<(NEDGES + 255) / 256, 256>>>(edst);
    build_rowptr_kernel<<<1, 1024>>>();
    fill_csr_kernel<<<(NEDGES + 255) / 256, 256>>>(esrc, edst);

    // conversions
    zero_pad_kernel<<<MPAD - NNODES, 256>>>();
    convertX_kernel<<<NNODES, 256>>>(x);
    dim3 tgrid(32, 32), tblk(32, 8);
    transposeW_kernel<<<tgrid, tblk>>>(Ws0, 0);
    transposeW_kernel<<<tgrid, tblk>>>(Wn0, DIM);

    dim3 ggrid(DIM / 128, MPAD / 128);   // (8, 196)

    // layer 0: h (fp16) -> A1 cols [0,1024)
    aggregate_f32_kernel<<<NNODES, 256>>>(x);
    gemm_f16_kernel<<<ggrid, 256, SMEMSZ>>>(a0, b0, nullptr, a1, NNODES, 1);

    // layer 1 weight transpose (independent of layer 0 results)
    transposeW_kernel<<<tgrid, tblk>>>(Ws1, 0);
    transposeW_kernel<<<tgrid, tblk>>>(Wn1, DIM);

    // layer 1
    aggregate_f16_kernel<<<NNODES, 256>>>();
    gemm_f16_kernel<<<ggrid, 256, SMEMSZ>>>(a1, b1, out, nullptr, NNODES, 0);
}

// round 12
// speedup vs baseline: 2.5475x; 1.0735x over previous
#include <cuda_runtime.h>
#include <cuda_fp16.h>
#include <cstdint>

#define NNODES 25000
#define NEDGES 400000
#define DIM    1024
#define MPAD   25088          // 196 * 128
#define KDUAL  2048
#define BK     64
#define NSTAGE (KDUAL / BK)   // 32
#define NBUF   3
#define STAGE_BYTES 32768     // A 16K + B 16K
#define SMEMSZ (NBUF * STAGE_BYTES + 1024)

// ---------------- device scratch ---------------------------------------------
__device__ int   g_deg[NNODES];
__device__ float g_deginv[NNODES];
__device__ int   g_rowptr[NNODES + 1];
__device__ int   g_fill[NNODES];
__device__ int   g_col[NEDGES];
__device__ __align__(256) __half g_A0[(size_t)MPAD * KDUAL];   // [x | mean(x)] fp16
__device__ __align__(256) __half g_A1[(size_t)MPAD * KDUAL];   // [h | mean(h)] fp16
__device__ __align__(256) __half g_B[(size_t)DIM * KDUAL];     // [N][K] = fp16(W^T)

// ---------------- helpers ------------------------------------------------------
__device__ __forceinline__ uint32_t smem_u32_of(const void* p) {
    uint32_t a;
    asm("{ .reg .u64 t; cvta.to.shared.u64 t, %1; cvt.u32.u64 %0, t; }" : "=r"(a) : "l"(p));
    return a;
}

__device__ __forceinline__ uint32_t sw128(uint32_t off) {
    return off ^ ((off >> 3) & 0x70);
}

__device__ __forceinline__ void cp_async16(uint32_t saddr, const void* g) {
    asm volatile("cp.async.cg.shared.global [%0], [%1], 16;" :: "r"(saddr), "l"(g));
}

__device__ __forceinline__ void ldsm_x4(uint32_t* r, uint32_t addr) {
    asm volatile("ldmatrix.sync.aligned.m8n8.x4.shared.b16 {%0,%1,%2,%3}, [%4];"
                 : "=r"(r[0]), "=r"(r[1]), "=r"(r[2]), "=r"(r[3]) : "r"(addr));
}

__device__ __forceinline__ void mma_f16(float* d, const uint32_t* a, const uint32_t* b) {
    asm volatile(
        "mma.sync.aligned.m16n8k16.row.col.f32.f16.f16.f32 "
        "{%0,%1,%2,%3}, {%4,%5,%6,%7}, {%8,%9}, {%0,%1,%2,%3};"
        : "+f"(d[0]), "+f"(d[1]), "+f"(d[2]), "+f"(d[3])
        : "r"(a[0]), "r"(a[1]), "r"(a[2]), "r"(a[3]), "r"(b[0]), "r"(b[1]));
}

// ---------------- CSR build ---------------------------------------------------
__global__ void zero_deg_kernel() {
    int i = blockIdx.x * blockDim.x + threadIdx.x;
    if (i < NNODES) g_deg[i] = 0;
}

__global__ void count_deg_kernel(const int* __restrict__ edge_dst) {
    int e = blockIdx.x * blockDim.x + threadIdx.x;
    if (e < NEDGES) atomicAdd(&g_deg[edge_dst[e]], 1);
}

__global__ void build_rowptr_kernel() {
    __shared__ int sums[1024];
    const int tid = threadIdx.x;
    const int CHUNK = 25;
    const int start = tid * CHUNK;
    int s = 0;
    for (int i = 0; i < CHUNK; ++i) {
        int idx = start + i;
        if (idx < NNODES) s += g_deg[idx];
    }
    sums[tid] = s;
    __syncthreads();
    for (int off = 1; off < 1024; off <<= 1) {
        int add = 0;
        if (tid >= off) add = sums[tid - off];
        __syncthreads();
        sums[tid] += add;
        __syncthreads();
    }
    int prefix = (tid > 0) ? sums[tid - 1] : 0;
    for (int i = 0; i < CHUNK; ++i) {
        int idx = start + i;
        if (idx < NNODES) {
            g_rowptr[idx] = prefix;
            int d = g_deg[idx];
            prefix += d;
            g_deginv[idx] = 1.0f / fmaxf((float)d, 1.0f);
            g_fill[idx] = 0;
        }
    }
    if (tid == 1023) g_rowptr[NNODES] = sums[1023];
}

__global__ void fill_csr_kernel(const int* __restrict__ edge_src,
                                const int* __restrict__ edge_dst) {
    int e = blockIdx.x * blockDim.x + threadIdx.x;
    if (e < NEDGES) {
        int dst = edge_dst[e];
        int pos = g_rowptr[dst] + atomicAdd(&g_fill[dst], 1);
        g_col[pos] = edge_src[e];
    }
}

// ---------------- conversions --------------------------------------------------
__device__ __forceinline__ void store4_f16(__half* dst, size_t off, float4 v) {
    __half2 h0; h0.x = __float2half_rn(v.x); h0.y = __float2half_rn(v.y);
    __half2 h1; h1.x = __float2half_rn(v.z); h1.y = __float2half_rn(v.w);
    *reinterpret_cast<__half2*>(dst + off)     = h0;
    *reinterpret_cast<__half2*>(dst + off + 2) = h1;
}

__global__ void zero_pad_kernel() {
    int row = NNODES + blockIdx.x;          // 88 blocks
    int t = threadIdx.x;
    size_t off = (size_t)row * KDUAL + t * 8;
    uint4 z = make_uint4(0, 0, 0, 0);
    *reinterpret_cast<uint4*>(g_A0 + off) = z;
    *reinterpret_cast<uint4*>(g_A1 + off) = z;
}

__global__ __launch_bounds__(256) void convertX_kernel(const float* __restrict__ x) {
    int row = blockIdx.x, t = threadIdx.x;
    float4 v = ((const float4*)(x + (size_t)row * DIM))[t];
    store4_f16(g_A0, (size_t)row * KDUAL + t * 4, v);
}

// W[k][n] fp32 -> B^T[n][koff+k] fp16
__global__ void transposeW_kernel(const float* __restrict__ W, int koff) {
    __shared__ float tile[32][33];
    int tx = threadIdx.x, ty = threadIdx.y;       // (32, 8)
    int nb = blockIdx.x * 32, kb = blockIdx.y * 32;
    #pragma unroll
    for (int i = 0; i < 32; i += 8)
        tile[ty + i][tx] = W[(size_t)(kb + ty + i) * DIM + nb + tx];
    __syncthreads();
    #pragma unroll
    for (int i = 0; i < 32; i += 8) {
        float v = tile[tx][ty + i];
        g_B[(size_t)(nb + ty + i) * KDUAL + koff + kb + tx] = __float2half_rn(v);
    }
}

// ---------------- aggregation ---------------------------------------------------
// gather fp16 rows from a[.][0,1024), fp32 accumulate, mean -> fp16 a[.][1024,2048)
__global__ __launch_bounds__(256)
void aggregate_f16_kernel(__half* __restrict__ a) {
    const int node = blockIdx.x;
    const int tid  = threadIdx.x;
    const int beg = g_rowptr[node];
    const int end = g_rowptr[node + 1];
    float4 acc0 = make_float4(0.f, 0.f, 0.f, 0.f);
    float4 acc1 = make_float4(0.f, 0.f, 0.f, 0.f);
    int i = beg;
    for (; i + 1 < end; i += 2) {
        int s0 = g_col[i], s1 = g_col[i + 1];
        uint2 r0 = *reinterpret_cast<const uint2*>(a + (size_t)s0 * KDUAL + tid * 4);
        uint2 r1 = *reinterpret_cast<const uint2*>(a + (size_t)s1 * KDUAL + tid * 4);
        float2 a0 = __half22float2(*reinterpret_cast<__half2*>(&r0.x));
        float2 b0 = __half22float2(*reinterpret_cast<__half2*>(&r0.y));
        float2 a1 = __half22float2(*reinterpret_cast<__half2*>(&r1.x));
        float2 b1 = __half22float2(*reinterpret_cast<__half2*>(&r1.y));
        acc0.x += a0.x; acc0.y += a0.y; acc0.z += b0.x; acc0.w += b0.y;
        acc1.x += a1.x; acc1.y += a1.y; acc1.z += b1.x; acc1.w += b1.y;
    }
    if (i < end) {
        int s0 = g_col[i];
        uint2 r0 = *reinterpret_cast<const uint2*>(a + (size_t)s0 * KDUAL + tid * 4);
        float2 a0 = __half22float2(*reinterpret_cast<__half2*>(&r0.x));
        float2 b0 = __half22float2(*reinterpret_cast<__half2*>(&r0.y));
        acc0.x += a0.x; acc0.y += a0.y; acc0.z += b0.x; acc0.w += b0.y;
    }
    float di = g_deginv[node];
    acc0.x = (acc0.x + acc1.x) * di;
    acc0.y = (acc0.y + acc1.y) * di;
    acc0.z = (acc0.z + acc1.z) * di;
    acc0.w = (acc0.w + acc1.w) * di;
    store4_f16(a, (size_t)node * KDUAL + DIM + tid * 4, acc0);
}

// ---------------- mma.sync fp16 GEMM (single product) ----------------------------
// C[M,1024] = A @ B^T + bias; 128x128 CTA tile, BK=64, 3-stage, 8 warps 64x32.
__global__ __launch_bounds__(256)
void gemm_f16_kernel(const __half* __restrict__ A,
                     const float* __restrict__ bias,
                     float* __restrict__ C,
                     __half* __restrict__ OutH,
                     int M, int relu) {
    extern __shared__ __align__(1024) char smem_raw[];
    const uint32_t base = (smem_u32_of(smem_raw) + 1023u) & ~1023u;

    const int t = threadIdx.x;
    const int lane = t & 31;
    const int w = t >> 5;
    const int wm = w >> 2;            // 0..1 -> M offset wm*64
    const int wn = w & 3;             // 0..3 -> N offset wn*32
    const int m0 = blockIdx.y * 128;
    const int n0 = blockIdx.x * 128;

    const char* pA = (const char*)A + (size_t)m0 * 4096;
    const char* pB = (const char*)g_B + (size_t)n0 * 4096;

    float acc[4][4][4];
    #pragma unroll
    for (int i = 0; i < 4; ++i)
        #pragma unroll
        for (int j = 0; j < 4; ++j)
            #pragma unroll
            for (int r = 0; r < 4; ++r) acc[i][j][r] = 0.f;

    const int rowA = lane & 15;
    const int csA  = lane >> 4;
    const int rowB = (lane & 7) | ((lane & 16) >> 1);
    const int csB  = (lane >> 3) & 1;

    // stage: A tile 128x64 fp16 (128B rows, SW128) @0, B tile @16384
    auto load_stage = [&](int s) {
        uint32_t sb = base + (s % NBUF) * STAGE_BYTES;
        size_t kb = (size_t)s * 128;          // BK*2 bytes along K
        #pragma unroll
        for (int i = 0; i < 4; ++i) {
            int c = t + i * 256;              // 1024 chunks of 16B per tile
            int row = c >> 3, col = (c & 7) * 16;
            uint32_t so = sw128((uint32_t)(row * 128 + col));
            size_t go = (size_t)row * 4096 + col + kb;
            cp_async16(sb + so,         pA + go);
            cp_async16(sb + 16384 + so, pB + go);
        }
        asm volatile("cp.async.commit_group;" ::: "memory");
    };

    load_stage(0);
    load_stage(1);

    #pragma unroll 1
    for (int s = 0; s < NSTAGE; ++s) {
        if (s == NSTAGE - 1)
            asm volatile("cp.async.wait_group 0;" ::: "memory");
        else
            asm volatile("cp.async.wait_group 1;" ::: "memory");
        __syncthreads();
        if (s + 2 < NSTAGE) load_stage(s + 2);   // buf (s+2)%3: compute(s-1) done

        uint32_t sb = base + (s % NBUF) * STAGE_BYTES;
        const uint32_t sA = sb, sB = sb + 16384;

        #pragma unroll
        for (int kk = 0; kk < 4; ++kk) {
            uint32_t ah[4][4];
            #pragma unroll
            for (int mf = 0; mf < 4; ++mf) {
                int row = wm * 64 + mf * 16 + rowA;
                ldsm_x4(ah[mf], sA + sw128((uint32_t)(row * 128 + (kk * 2 + csA) * 16)));
            }
            #pragma unroll
            for (int nh = 0; nh < 2; ++nh) {
                int row = wn * 32 + nh * 16 + rowB;
                uint32_t rh[4];
                ldsm_x4(rh, sB + sw128((uint32_t)(row * 128 + (kk * 2 + csB) * 16)));
                #pragma unroll
                for (int mf = 0; mf < 4; ++mf) {
                    mma_f16(acc[mf][nh * 2],     ah[mf], rh);
                    mma_f16(acc[mf][nh * 2 + 1], ah[mf], rh + 2);
                }
            }
        }
        __syncthreads();
    }

    // ---------------- epilogue ----------------
    const int r_in = lane >> 2;
    const int c_in = (lane & 3) * 2;
    #pragma unroll
    for (int mf = 0; mf < 4; ++mf) {
        int mA = m0 + wm * 64 + mf * 16 + r_in;
        int mB = mA + 8;
        #pragma unroll
        for (int nf = 0; nf < 4; ++nf) {
            int n = n0 + wn * 32 + nf * 8 + c_in;
            float bx = bias[n], by = bias[n + 1];
            float v0 = acc[mf][nf][0] + bx, v1 = acc[mf][nf][1] + by;
            float v2 = acc[mf][nf][2] + bx, v3 = acc[mf][nf][3] + by;
            if (relu) {
                v0 = fmaxf(v0, 0.f); v1 = fmaxf(v1, 0.f);
                v2 = fmaxf(v2, 0.f); v3 = fmaxf(v3, 0.f);
            }
            if (mA < M) {
                if (C) *(float2*)(C + (size_t)mA * DIM + n) = make_float2(v0, v1);
                if (OutH) {
                    __half2 h; h.x = __float2half_rn(v0); h.y = __float2half_rn(v1);
                    *reinterpret_cast<__half2*>(OutH + (size_t)mA * KDUAL + n) = h;
                }
            }
            if (mB < M) {
                if (C) *(float2*)(C + (size_t)mB * DIM + n) = make_float2(v2, v3);
                if (OutH) {
                    __half2 h; h.x = __float2half_rn(v2); h.y = __float2half_rn(v3);
                    *reinterpret_cast<__half2*>(OutH + (size_t)mB * KDUAL + n) = h;
                }
            }
        }
    }
}

// ---------------- launch --------------------------------------------------------
extern "C" void kernel_launch(void* const* d_in, const int* in_sizes, int n_in,
                              void* d_out, int out_size) {
    const float* x    = (const float*)d_in[0];
    const int*   esrc = (const int*)d_in[1];
    const int*   edst = (const int*)d_in[2];
    const float* Ws0  = (const float*)d_in[3];
    const float* Wn0  = (const float*)d_in[4];
    const float* b0   = (const float*)d_in[5];
    const float* Ws1  = (const float*)d_in[6];
    const float* Wn1  = (const float*)d_in[7];
    const float* b1   = (const float*)d_in[8];
    float* out = (float*)d_out;

    __half *a0, *a1;
    cudaGetSymbolAddress((void**)&a0, g_A0);
    cudaGetSymbolAddress((void**)&a1, g_A1);

    cudaFuncSetAttribute(gemm_f16_kernel,
                         cudaFuncAttributeMaxDynamicSharedMemorySize, SMEMSZ);

    // CSR
    zero_deg_kernel<<<(NNODES + 255) / 256, 256>>>();
    count_deg_kernel<<<(NEDGES + 255) / 256, 256>>>(edst);
    build_rowptr_kernel<<<1, 1024>>>();
    fill_csr_kernel<<<(NEDGES + 255) / 256, 256>>>(esrc, edst);

    // conversions (x -> fp16 A0 first; aggregation then gathers fp16)
    zero_pad_kernel<<<MPAD - NNODES, 256>>>();
    convertX_kernel<<<NNODES, 256>>>(x);
    dim3 tgrid(32, 32), tblk(32, 8);
    transposeW_kernel<<<tgrid, tblk>>>(Ws0, 0);
    transposeW_kernel<<<tgrid, tblk>>>(Wn0, DIM);

    dim3 ggrid(DIM / 128, MPAD / 128);   // (8, 196)

    // layer 0: mean from fp16 x; h (fp16) -> A1 cols [0,1024)
    aggregate_f16_kernel<<<NNODES, 256>>>(a0);
    gemm_f16_kernel<<<ggrid, 256, SMEMSZ>>>(a0, b0, nullptr, a1, NNODES, 1);

    // layer 1 weight transpose (independent of layer 0 results)
    transposeW_kernel<<<tgrid, tblk>>>(Ws1, 0);
    transposeW_kernel<<<tgrid, tblk>>>(Wn1, DIM);

    // layer 1
    aggregate_f16_kernel<<<NNODES, 256>>>(a1);
    gemm_f16_kernel<<<ggrid, 256, SMEMSZ>>>(a1, b1, out, nullptr, NNODES, 0);
}

// round 13
// speedup vs baseline: 2.7364x; 1.0741x over previous
#include <cuda_runtime.h>
#include <cuda_fp16.h>
#include <cstdint>

#define NNODES 25000
#define NEDGES 400000
#define DIM    1024
#define MPAD   25088          // 196 * 128
#define KDUAL  2048
#define BK     64
#define NSTAGE (KDUAL / BK)   // 32
#define NBUF   3
#define STAGE_BYTES 24576     // A 16K + B 8K
#define SMEMSZ (NBUF * STAGE_BYTES + 1024)

// ---------------- device scratch ---------------------------------------------
__device__ int   g_deg[NNODES];
__device__ float g_deginv[NNODES];
__device__ int   g_rowptr[NNODES + 1];
__device__ int   g_fill[NNODES];
__device__ int   g_col[NEDGES];
__device__ __align__(256) __half g_A0[(size_t)MPAD * KDUAL];   // [x | mean(x)] fp16
__device__ __align__(256) __half g_A1[(size_t)MPAD * KDUAL];   // [h | mean(h)] fp16
__device__ __align__(256) __half g_B0[(size_t)DIM * KDUAL];    // layer-0 [N][K] fp16(W^T)
__device__ __align__(256) __half g_B1[(size_t)DIM * KDUAL];    // layer-1 [N][K] fp16(W^T)

// ---------------- helpers ------------------------------------------------------
__device__ __forceinline__ uint32_t smem_u32_of(const void* p) {
    uint32_t a;
    asm("{ .reg .u64 t; cvta.to.shared.u64 t, %1; cvt.u32.u64 %0, t; }" : "=r"(a) : "l"(p));
    return a;
}

__device__ __forceinline__ uint32_t sw128(uint32_t off) {
    return off ^ ((off >> 3) & 0x70);
}

__device__ __forceinline__ void cp_async16(uint32_t saddr, const void* g) {
    asm volatile("cp.async.cg.shared.global [%0], [%1], 16;" :: "r"(saddr), "l"(g));
}

__device__ __forceinline__ void ldsm_x4(uint32_t* r, uint32_t addr) {
    asm volatile("ldmatrix.sync.aligned.m8n8.x4.shared.b16 {%0,%1,%2,%3}, [%4];"
                 : "=r"(r[0]), "=r"(r[1]), "=r"(r[2]), "=r"(r[3]) : "r"(addr));
}

__device__ __forceinline__ void mma_f16(float* d, const uint32_t* a, const uint32_t* b) {
    asm volatile(
        "mma.sync.aligned.m16n8k16.row.col.f32.f16.f16.f32 "
        "{%0,%1,%2,%3}, {%4,%5,%6,%7}, {%8,%9}, {%0,%1,%2,%3};"
        : "+f"(d[0]), "+f"(d[1]), "+f"(d[2]), "+f"(d[3])
        : "r"(a[0]), "r"(a[1]), "r"(a[2]), "r"(a[3]), "r"(b[0]), "r"(b[1]));
}

// ---------------- CSR build ---------------------------------------------------
// blocks [0,88): zero pad rows of A0/A1; blocks [88,98): zero g_deg
__global__ void zero_init_kernel() {
    if (blockIdx.x < 88) {
        int row = NNODES + blockIdx.x;
        size_t off = (size_t)row * KDUAL + threadIdx.x * 8;
        uint4 z = make_uint4(0, 0, 0, 0);
        *reinterpret_cast<uint4*>(g_A0 + off) = z;
        *reinterpret_cast<uint4*>(g_A1 + off) = z;
    } else {
        int i = (blockIdx.x - 88) * 256 + threadIdx.x;   // 0..2559
        for (int k = i; k < NNODES; k += 2560) g_deg[k] = 0;
    }
}

__global__ void count_deg_kernel(const int* __restrict__ edge_dst) {
    int e = blockIdx.x * blockDim.x + threadIdx.x;
    if (e < NEDGES) atomicAdd(&g_deg[edge_dst[e]], 1);
}

__global__ void build_rowptr_kernel() {
    __shared__ int sums[1024];
    const int tid = threadIdx.x;
    const int CHUNK = 25;
    const int start = tid * CHUNK;
    int s = 0;
    for (int i = 0; i < CHUNK; ++i) {
        int idx = start + i;
        if (idx < NNODES) s += g_deg[idx];
    }
    sums[tid] = s;
    __syncthreads();
    for (int off = 1; off < 1024; off <<= 1) {
        int add = 0;
        if (tid >= off) add = sums[tid - off];
        __syncthreads();
        sums[tid] += add;
        __syncthreads();
    }
    int prefix = (tid > 0) ? sums[tid - 1] : 0;
    for (int i = 0; i < CHUNK; ++i) {
        int idx = start + i;
        if (idx < NNODES) {
            g_rowptr[idx] = prefix;
            int d = g_deg[idx];
            prefix += d;
            g_deginv[idx] = 1.0f / fmaxf((float)d, 1.0f);
            g_fill[idx] = 0;
        }
    }
    if (tid == 1023) g_rowptr[NNODES] = sums[1023];
}

__global__ void fill_csr_kernel(const int* __restrict__ edge_src,
                                const int* __restrict__ edge_dst) {
    int e = blockIdx.x * blockDim.x + threadIdx.x;
    if (e < NEDGES) {
        int dst = edge_dst[e];
        int pos = g_rowptr[dst] + atomicAdd(&g_fill[dst], 1);
        g_col[pos] = edge_src[e];
    }
}

// ---------------- conversions --------------------------------------------------
__global__ __launch_bounds__(256) void convertX_kernel(const float* __restrict__ x) {
    int row = blockIdx.x, t = threadIdx.x;
    float4 v = ((const float4*)(x + (size_t)row * DIM))[t];
    __half2 h0; h0.x = __float2half_rn(v.x); h0.y = __float2half_rn(v.y);
    __half2 h1; h1.x = __float2half_rn(v.z); h1.y = __float2half_rn(v.w);
    size_t off = (size_t)row * KDUAL + t * 4;
    *reinterpret_cast<__half2*>(g_A0 + off)     = h0;
    *reinterpret_cast<__half2*>(g_A0 + off + 2) = h1;
}

// all four W[k][n] fp32 -> B^T[n][koff+k] fp16; z selects (layer, self/neigh)
__global__ void transpose_all_kernel(const float* __restrict__ Ws0,
                                     const float* __restrict__ Wn0,
                                     const float* __restrict__ Ws1,
                                     const float* __restrict__ Wn1) {
    __shared__ float tile[32][33];
    int z = blockIdx.z;
    const float* W = (z == 0) ? Ws0 : (z == 1) ? Wn0 : (z == 2) ? Ws1 : Wn1;
    __half* B = (z < 2) ? g_B0 : g_B1;
    int koff = (z & 1) * DIM;
    int tx = threadIdx.x, ty = threadIdx.y;       // (32, 8)
    int nb = blockIdx.x * 32, kb = blockIdx.y * 32;
    #pragma unroll
    for (int i = 0; i < 32; i += 8)
        tile[ty + i][tx] = W[(size_t)(kb + ty + i) * DIM + nb + tx];
    __syncthreads();
    #pragma unroll
    for (int i = 0; i < 32; i += 8) {
        float v = tile[tx][ty + i];
        B[(size_t)(nb + ty + i) * KDUAL + koff + kb + tx] = __float2half_rn(v);
    }
}

// ---------------- aggregation ---------------------------------------------------
// gather fp16 rows from a[.][0,1024), fp32 accumulate, mean -> fp16 a[.][1024,2048)
// 128 threads, 16B per thread per row.
__global__ __launch_bounds__(128)
void aggregate_f16_kernel(__half* __restrict__ a) {
    const int node = blockIdx.x;
    const int tid  = threadIdx.x;
    const int beg = g_rowptr[node];
    const int end = g_rowptr[node + 1];
    float acc0[8] = {0.f, 0.f, 0.f, 0.f, 0.f, 0.f, 0.f, 0.f};
    float acc1[8] = {0.f, 0.f, 0.f, 0.f, 0.f, 0.f, 0.f, 0.f};
    int i = beg;
    for (; i + 1 < end; i += 2) {
        int s0 = g_col[i], s1 = g_col[i + 1];
        uint4 r0 = *reinterpret_cast<const uint4*>(a + (size_t)s0 * KDUAL + tid * 8);
        uint4 r1 = *reinterpret_cast<const uint4*>(a + (size_t)s1 * KDUAL + tid * 8);
        const uint32_t* p0 = &r0.x;
        const uint32_t* p1 = &r1.x;
        #pragma unroll
        for (int j = 0; j < 4; ++j) {
            float2 f0 = __half22float2(*reinterpret_cast<const __half2*>(&p0[j]));
            float2 f1 = __half22float2(*reinterpret_cast<const __half2*>(&p1[j]));
            acc0[j * 2]     += f0.x;
            acc0[j * 2 + 1] += f0.y;
            acc1[j * 2]     += f1.x;
            acc1[j * 2 + 1] += f1.y;
        }
    }
    if (i < end) {
        int s0 = g_col[i];
        uint4 r0 = *reinterpret_cast<const uint4*>(a + (size_t)s0 * KDUAL + tid * 8);
        const uint32_t* p0 = &r0.x;
        #pragma unroll
        for (int j = 0; j < 4; ++j) {
            float2 f0 = __half22float2(*reinterpret_cast<const __half2*>(&p0[j]));
            acc0[j * 2]     += f0.x;
            acc0[j * 2 + 1] += f0.y;
        }
    }
    float di = g_deginv[node];
    uint4 outw;
    uint32_t* po = &outw.x;
    #pragma unroll
    for (int j = 0; j < 4; ++j) {
        __half2 h;
        h.x = __float2half_rn((acc0[j * 2]     + acc1[j * 2])     * di);
        h.y = __float2half_rn((acc0[j * 2 + 1] + acc1[j * 2 + 1]) * di);
        po[j] = *reinterpret_cast<uint32_t*>(&h);
    }
    *reinterpret_cast<uint4*>(a + (size_t)node * KDUAL + DIM + tid * 8) = outw;
}

// ---------------- mma.sync fp16 GEMM ---------------------------------------------
// C[M,1024] = A @ B^T + bias; CTA 128x64, BK=64, 3-stage, 4 warps each 64x32.
// Grid (16, 196) = 3136 CTAs, 3 CTAs/SM -> 7.06 waves (no tail).
__global__ __launch_bounds__(128)
void gemm_f16_kernel(const __half* __restrict__ A,
                     const __half* __restrict__ B,
                     const float* __restrict__ bias,
                     float* __restrict__ C,
                     __half* __restrict__ OutH,
                     int M, int relu) {
    extern __shared__ __align__(1024) char smem_raw[];
    const uint32_t base = (smem_u32_of(smem_raw) + 1023u) & ~1023u;

    const int t = threadIdx.x;
    const int lane = t & 31;
    const int w = t >> 5;             // 0..3
    const int wm = w >> 1;            // 0..1 -> M offset wm*64
    const int wn = w & 1;             // 0..1 -> N offset wn*32
    const int m0 = blockIdx.y * 128;
    const int n0 = blockIdx.x * 64;

    const char* pA = (const char*)A + (size_t)m0 * 4096;
    const char* pB = (const char*)B + (size_t)n0 * 4096;

    float acc[4][4][4];
    #pragma unroll
    for (int i = 0; i < 4; ++i)
        #pragma unroll
        for (int j = 0; j < 4; ++j)
            #pragma unroll
            for (int r = 0; r < 4; ++r) acc[i][j][r] = 0.f;

    const int rowA = lane & 15;
    const int csA  = lane >> 4;
    const int rowB = (lane & 7) | ((lane & 16) >> 1);
    const int csB  = (lane >> 3) & 1;

    // stage: A tile 128x64 fp16 (128B rows, SW128) @0, B tile 64x64 @16384
    auto load_stage = [&](int s) {
        uint32_t sb = base + (s % NBUF) * STAGE_BYTES;
        size_t kb = (size_t)s * 128;          // BK*2 bytes along K
        #pragma unroll
        for (int i = 0; i < 8; ++i) {         // A: 1024 chunks of 16B
            int c = t + i * 128;
            int row = c >> 3, col = (c & 7) * 16;
            cp_async16(sb + sw128((uint32_t)(row * 128 + col)),
                       pA + (size_t)row * 4096 + col + kb);
        }
        #pragma unroll
        for (int i = 0; i < 4; ++i) {         // B: 512 chunks of 16B
            int c = t + i * 128;
            int row = c >> 3, col = (c & 7) * 16;
            cp_async16(sb + 16384 + sw128((uint32_t)(row * 128 + col)),
                       pB + (size_t)row * 4096 + col + kb);
        }
        asm volatile("cp.async.commit_group;" ::: "memory");
    };

    load_stage(0);
    load_stage(1);

    #pragma unroll 1
    for (int s = 0; s < NSTAGE; ++s) {
        if (s == NSTAGE - 1)
            asm volatile("cp.async.wait_group 0;" ::: "memory");
        else
            asm volatile("cp.async.wait_group 1;" ::: "memory");
        __syncthreads();
        if (s + 2 < NSTAGE) load_stage(s + 2);   // buf (s+2)%3: compute(s-1) done

        uint32_t sb = base + (s % NBUF) * STAGE_BYTES;
        const uint32_t sA = sb, sB = sb + 16384;

        #pragma unroll
        for (int kk = 0; kk < 4; ++kk) {
            uint32_t ah[4][4];
            #pragma unroll
            for (int mf = 0; mf < 4; ++mf) {
                int row = wm * 64 + mf * 16 + rowA;
                ldsm_x4(ah[mf], sA + sw128((uint32_t)(row * 128 + (kk * 2 + csA) * 16)));
            }
            #pragma unroll
            for (int nh = 0; nh < 2; ++nh) {
                int row = wn * 32 + nh * 16 + rowB;
                uint32_t rh[4];
                ldsm_x4(rh, sB + sw128((uint32_t)(row * 128 + (kk * 2 + csB) * 16)));
                #pragma unroll
                for (int mf = 0; mf < 4; ++mf) {
                    mma_f16(acc[mf][nh * 2],     ah[mf], rh);
                    mma_f16(acc[mf][nh * 2 + 1], ah[mf], rh + 2);
                }
            }
        }
        __syncthreads();
    }

    // ---------------- epilogue ----------------
    const int r_in = lane >> 2;
    const int c_in = (lane & 3) * 2;
    #pragma unroll
    for (int mf = 0; mf < 4; ++mf) {
        int mA = m0 + wm * 64 + mf * 16 + r_in;
        int mB = mA + 8;
        #pragma unroll
        for (int nf = 0; nf < 4; ++nf) {
            int n = n0 + wn * 32 + nf * 8 + c_in;
            float bx = bias[n], by = bias[n + 1];
            float v0 = acc[mf][nf][0] + bx, v1 = acc[mf][nf][1] + by;
            float v2 = acc[mf][nf][2] + bx, v3 = acc[mf][nf][3] + by;
            if (relu) {
                v0 = fmaxf(v0, 0.f); v1 = fmaxf(v1, 0.f);
                v2 = fmaxf(v2, 0.f); v3 = fmaxf(v3, 0.f);
            }
            if (mA < M) {
                if (C) *(float2*)(C + (size_t)mA * DIM + n) = make_float2(v0, v1);
                if (OutH) {
                    __half2 h; h.x = __float2half_rn(v0); h.y = __float2half_rn(v1);
                    *reinterpret_cast<__half2*>(OutH + (size_t)mA * KDUAL + n) = h;
                }
            }
            if (mB < M) {
                if (C) *(float2*)(C + (size_t)mB * DIM + n) = make_float2(v2, v3);
                if (OutH) {
                    __half2 h; h.x = __float2half_rn(v2); h.y = __float2half_rn(v3);
                    *reinterpret_cast<__half2*>(OutH + (size_t)mB * KDUAL + n) = h;
                }
            }
        }
    }
}

// ---------------- launch --------------------------------------------------------
extern "C" void kernel_launch(void* const* d_in, const int* in_sizes, int n_in,
                              void* d_out, int out_size) {
    const float* x    = (const float*)d_in[0];
    const int*   esrc = (const int*)d_in[1];
    const int*   edst = (const int*)d_in[2];
    const float* Ws0  = (const float*)d_in[3];
    const float* Wn0  = (const float*)d_in[4];
    const float* b0   = (const float*)d_in[5];
    const float* Ws1  = (const float*)d_in[6];
    const float* Wn1  = (const float*)d_in[7];
    const float* b1   = (const float*)d_in[8];
    float* out = (float*)d_out;

    __half *a0, *a1, *bw0, *bw1;
    cudaGetSymbolAddress((void**)&a0, g_A0);
    cudaGetSymbolAddress((void**)&a1, g_A1);
    cudaGetSymbolAddress((void**)&bw0, g_B0);
    cudaGetSymbolAddress((void**)&bw1, g_B1);

    cudaFuncSetAttribute(gemm_f16_kernel,
                         cudaFuncAttributeMaxDynamicSharedMemorySize, SMEMSZ);

    // CSR + init
    zero_init_kernel<<<98, 256>>>();
    count_deg_kernel<<<(NEDGES + 255) / 256, 256>>>(edst);
    build_rowptr_kernel<<<1, 1024>>>();
    fill_csr_kernel<<<(NEDGES + 255) / 256, 256>>>(esrc, edst);

    // conversions (x -> fp16 A0; all four weight transposes up front)
    convertX_kernel<<<NNODES, 256>>>(x);
    dim3 tgrid(32, 32, 4), tblk(32, 8);
    transpose_all_kernel<<<tgrid, tblk>>>(Ws0, Wn0, Ws1, Wn1);

    dim3 ggrid(DIM / 64, MPAD / 128);    // (16, 196)

    // layer 0: mean from fp16 x; h (fp16) -> A1 cols [0,1024)
    aggregate_f16_kernel<<<NNODES, 128>>>(a0);
    gemm_f16_kernel<<<ggrid, 128, SMEMSZ>>>(a0, bw0, b0, nullptr, a1, NNODES, 1);

    // layer 1
    aggregate_f16_kernel<<<NNODES, 128>>>(a1);
    gemm_f16_kernel<<<ggrid, 128, SMEMSZ>>>(a1, bw1, b1, out, nullptr, NNODES, 0);
}